// round 1
// baseline (speedup 1.0000x reference)
#include <cuda_runtime.h>
#include <math.h>

#define B_   32
#define NN   1024
#define FIN  512
#define H1_  256
#define H2_  128

// ---------------- scratch (device globals; no allocation allowed) ----------
__device__ float d_h1[B_ * NN * H1_];       // 33.5 MB
__device__ float d_g1[B_ * NN * H1_];       // 33.5 MB
__device__ float d_h2[B_ * NN * H2_];       // 16.8 MB
__device__ float d_att1[(long long)B_ * NN * NN]; // 134 MB
__device__ float d_el[B_ * NN];
__device__ float d_er[B_ * NN];
__device__ float d_stat[B_ * 2];            // (mn, k=30/(mx-mn)) per batch
__device__ float d_gv[B_ * NN];

// ---------------- generic tiled SGEMM: C[M,N] = A[M,K] @ B[K,N] ------------
// 64x64 block tile, BK=16, 256 threads, 4x4 micro-tile per thread.
// blockIdx.z = batch (strides sA/sB/sC). EPI: 0 = none, 1 = ELU.
template <int EPI>
__global__ void sgemm64(const float* __restrict__ A, const float* __restrict__ B,
                        float* __restrict__ C, int M, int N, int K,
                        long long sA, long long sB, long long sC)
{
    __shared__ float As[16][64];
    __shared__ float Bs[16][64];

    A += (long long)blockIdx.z * sA;
    B += (long long)blockIdx.z * sB;
    C += (long long)blockIdx.z * sC;

    const int m0 = blockIdx.y * 64;
    const int n0 = blockIdx.x * 64;
    const int tid = threadIdx.x;
    const int tx = tid & 15;          // 0..15 -> 4 cols each
    const int ty = tid >> 4;          // 0..15 -> 4 rows each

    const int arow = tid >> 2;        // 0..63
    const int aq   = (tid & 3) * 4;   // k offset 0,4,8,12
    const int brow = tid >> 4;        // 0..15
    const int bcol = (tid & 15) * 4;  // 0..60

    float acc[4][4] = {};

    for (int k0 = 0; k0 < K; k0 += 16) {
        float4 av = *(const float4*)&A[(long long)(m0 + arow) * K + k0 + aq];
        float4 bv = *(const float4*)&B[(long long)(k0 + brow) * N + n0 + bcol];
        As[aq + 0][arow] = av.x;
        As[aq + 1][arow] = av.y;
        As[aq + 2][arow] = av.z;
        As[aq + 3][arow] = av.w;
        *(float4*)&Bs[brow][bcol] = bv;
        __syncthreads();

#pragma unroll
        for (int k = 0; k < 16; k++) {
            float ar[4], br[4];
#pragma unroll
            for (int i = 0; i < 4; i++) ar[i] = As[k][ty * 4 + i];
#pragma unroll
            for (int j = 0; j < 4; j++) br[j] = Bs[k][tx * 4 + j];
#pragma unroll
            for (int i = 0; i < 4; i++)
#pragma unroll
                for (int j = 0; j < 4; j++)
                    acc[i][j] = fmaf(ar[i], br[j], acc[i][j]);
        }
        __syncthreads();
    }

#pragma unroll
    for (int i = 0; i < 4; i++) {
        float4 v;
        v.x = acc[i][0]; v.y = acc[i][1]; v.z = acc[i][2]; v.w = acc[i][3];
        if (EPI == 1) {  // ELU
            v.x = v.x > 0.f ? v.x : (__expf(v.x) - 1.f);
            v.y = v.y > 0.f ? v.y : (__expf(v.y) - 1.f);
            v.z = v.z > 0.f ? v.z : (__expf(v.z) - 1.f);
            v.w = v.w > 0.f ? v.w : (__expf(v.w) - 1.f);
        }
        const int m = m0 + ty * 4 + i;
        *(float4*)&C[(long long)m * N + n0 + tx * 4] = v;
    }
}

// ---------------- per-row dual dot: el = h.aL, er = h.aR --------------------
__global__ void rowdot(const float* __restrict__ h, const float* __restrict__ a,
                       float* __restrict__ el, float* __restrict__ er, int Fo)
{
    const int row  = (blockIdx.x * blockDim.x + threadIdx.x) >> 5;
    const int lane = threadIdx.x & 31;
    const float* hp = h + (long long)row * Fo;
    float sl = 0.f, sr = 0.f;
    for (int c = lane; c < Fo; c += 32) {
        float v = hp[c];
        sl = fmaf(v, a[c], sl);
        sr = fmaf(v, a[Fo + c], sr);
    }
#pragma unroll
    for (int o = 16; o; o >>= 1) {
        sl += __shfl_xor_sync(0xFFFFFFFFu, sl, o);
        sr += __shfl_xor_sync(0xFFFFFFFFu, sr, o);
    }
    if (lane == 0) { el[row] = sl; er[row] = sr; }
}

// ---------------- per-batch min/max of separable e --------------------------
__global__ void minmax_stats(const float* __restrict__ el, const float* __restrict__ er,
                             float* __restrict__ stat)
{
    const int b = blockIdx.x;
    const int tid = threadIdx.x;
    float mnl = 1e30f, mxl = -1e30f, mnr = 1e30f, mxr = -1e30f;
    for (int i = tid; i < NN; i += 256) {
        float l = el[b * NN + i], r = er[b * NN + i];
        mnl = fminf(mnl, l); mxl = fmaxf(mxl, l);
        mnr = fminf(mnr, r); mxr = fmaxf(mxr, r);
    }
#pragma unroll
    for (int o = 16; o; o >>= 1) {
        mnl = fminf(mnl, __shfl_xor_sync(0xFFFFFFFFu, mnl, o));
        mxl = fmaxf(mxl, __shfl_xor_sync(0xFFFFFFFFu, mxl, o));
        mnr = fminf(mnr, __shfl_xor_sync(0xFFFFFFFFu, mnr, o));
        mxr = fmaxf(mxr, __shfl_xor_sync(0xFFFFFFFFu, mxr, o));
    }
    __shared__ float s[4][8];
    const int w = tid >> 5, lane = tid & 31;
    if (lane == 0) { s[0][w] = mnl; s[1][w] = mxl; s[2][w] = mnr; s[3][w] = mxr; }
    __syncthreads();
    if (tid == 0) {
        float a0 = s[0][0], a1 = s[1][0], a2 = s[2][0], a3 = s[3][0];
#pragma unroll
        for (int i = 1; i < 8; i++) {
            a0 = fminf(a0, s[0][i]); a1 = fmaxf(a1, s[1][i]);
            a2 = fminf(a2, s[2][i]); a3 = fmaxf(a3, s[3][i]);
        }
        float lo = a0 + a2, hi = a1 + a3;            // min/max of el_i + er_j (separable)
        float mn = lo >= 0.f ? lo : 0.01f * lo;      // leaky is monotone increasing
        float mx = hi >= 0.f ? hi : 0.01f * hi;
        stat[b * 2 + 0] = mn;
        stat[b * 2 + 1] = 30.f / (mx - mn);
    }
}

// ---------------- attention matrix: sigmoid((leaky(el+er)-mn)*k - 20) -------
__global__ void att_kernel(const float* __restrict__ el, const float* __restrict__ er,
                           const float* __restrict__ stat, float* __restrict__ att)
{
    const long long idx = ((long long)blockIdx.x * blockDim.x + threadIdx.x) * 4;
    const int b = (int)(idx >> 20);          // NN*NN = 2^20
    const int i = (int)(idx >> 10) & 1023;
    const int j = (int)idx & 1023;
    const float e  = el[b * NN + i];
    const float mn = stat[b * 2 + 0];
    const float k  = stat[b * 2 + 1];
    float4 r = *(const float4*)&er[b * NN + j];
    float4 o;
    {
        float x = e + r.x; float lr = x >= 0.f ? x : 0.01f * x;
        o.x = 1.f / (1.f + __expf(-(fmaf(lr - mn, k, -20.f))));
    }
    {
        float x = e + r.y; float lr = x >= 0.f ? x : 0.01f * x;
        o.y = 1.f / (1.f + __expf(-(fmaf(lr - mn, k, -20.f))));
    }
    {
        float x = e + r.z; float lr = x >= 0.f ? x : 0.01f * x;
        o.z = 1.f / (1.f + __expf(-(fmaf(lr - mn, k, -20.f))));
    }
    {
        float x = e + r.w; float lr = x >= 0.f ? x : 0.01f * x;
        o.w = 1.f / (1.f + __expf(-(fmaf(lr - mn, k, -20.f))));
    }
    *(float4*)&att[idx] = o;
}

// ---------------- gv = g2 @ Wg (warp per row, 128 elems) --------------------
__global__ void gv_kernel(const float* __restrict__ g2, const float* __restrict__ Wg,
                          float* __restrict__ gv)
{
    const int row  = (blockIdx.x * blockDim.x + threadIdx.x) >> 5;
    const int lane = threadIdx.x & 31;
    const float* gp = g2 + (long long)row * H2_;
    float s = fmaf(gp[lane], Wg[lane], gp[lane + 32] * Wg[lane + 32]);
    s = fmaf(gp[lane + 64], Wg[lane + 64], s);
    s = fmaf(gp[lane + 96], Wg[lane + 96], s);
#pragma unroll
    for (int o = 16; o; o >>= 1) s += __shfl_xor_sync(0xFFFFFFFFu, s, o);
    if (lane == 0) gv[row] = s;
}

// ---------------- out = leaky(fc2 @ gv + bg) (warp per row) -----------------
__global__ void z_kernel(const float* __restrict__ fc2, const float* __restrict__ gv,
                         const float* __restrict__ bg, float* __restrict__ out)
{
    const int row  = (blockIdx.x * blockDim.x + threadIdx.x) >> 5;
    const int lane = threadIdx.x & 31;
    const int b = row >> 10;
    const float* fr = fc2 + (long long)row * NN;
    const float* gr = gv + b * NN;
    float s = 0.f;
#pragma unroll
    for (int j = lane * 4; j < NN; j += 128) {
        float4 f = *(const float4*)&fr[j];
        float4 g = *(const float4*)&gr[j];
        s = fmaf(f.x, g.x, s); s = fmaf(f.y, g.y, s);
        s = fmaf(f.z, g.z, s); s = fmaf(f.w, g.w, s);
    }
#pragma unroll
    for (int o = 16; o; o >>= 1) s += __shfl_xor_sync(0xFFFFFFFFu, s, o);
    if (lane == 0) {
        float z = s + bg[0];
        out[row] = z >= 0.f ? z : 0.01f * z;
    }
}

// ---------------------------------------------------------------------------
static float* sym_f(const void* s)
{
    void* p = nullptr;
    cudaGetSymbolAddress(&p, s);
    return (float*)p;
}

extern "C" void kernel_launch(void* const* d_in, const int* in_sizes, int n_in,
                              void* d_out, int out_size)
{
    const float* x  = (const float*)d_in[0];
    // d_in[1] = edge_weight (unused by the reference network)
    const float* W1 = (const float*)d_in[2];
    const float* a1 = (const float*)d_in[3];
    const float* W2 = (const float*)d_in[4];
    const float* a2 = (const float*)d_in[5];
    const float* Wg = (const float*)d_in[6];
    const float* bg = (const float*)d_in[7];

    float* out = (float*)d_out;                        // [B,N,1]  = 32768
    float* fc2 = out + (long long)B_ * NN;             // [B,N,N]  = 33554432
    float* g2  = fc2 + (long long)B_ * NN * NN;        // [B,N,H2] = 4194304

    float* h1   = sym_f(d_h1);
    float* g1   = sym_f(d_g1);
    float* h2   = sym_f(d_h2);
    float* att1 = sym_f(d_att1);
    float* el   = sym_f(d_el);
    float* er   = sym_f(d_er);
    float* stat = sym_f(d_stat);
    float* gv   = sym_f(d_gv);

    const dim3 blk(256);
    const int rowsTot = B_ * NN;           // 32768

    // ===== Layer 1 =====
    // h1 = x @ W1   [32768,512]x[512,256]
    sgemm64<0><<<dim3(H1_ / 64, rowsTot / 64, 1), blk>>>(
        x, W1, h1, rowsTot, H1_, FIN, 0, 0, 0);
    rowdot<<<rowsTot / 8, 256>>>(h1, a1, el, er, H1_);
    minmax_stats<<<B_, 256>>>(el, er, stat);
    att_kernel<<<(int)(((long long)B_ * NN * NN / 4) / 256), 256>>>(el, er, stat, att1);
    // g1 = elu(att1 @ h1)   batched [1024,1024]x[1024,256]
    sgemm64<1><<<dim3(H1_ / 64, NN / 64, B_), blk>>>(
        att1, h1, g1, NN, H1_, NN,
        (long long)NN * NN, (long long)NN * H1_, (long long)NN * H1_);

    // ===== Layer 2 =====
    // h2 = g1 @ W2   [32768,256]x[256,128]
    sgemm64<0><<<dim3(H2_ / 64, rowsTot / 64, 1), blk>>>(
        g1, W2, h2, rowsTot, H2_, H1_, 0, 0, 0);
    rowdot<<<rowsTot / 8, 256>>>(h2, a2, el, er, H2_);
    minmax_stats<<<B_, 256>>>(el, er, stat);
    // fc2 (output) = attention of layer 2
    att_kernel<<<(int)(((long long)B_ * NN * NN / 4) / 256), 256>>>(el, er, stat, fc2);
    // g2 (output) = fc2 @ h2   batched [1024,1024]x[1024,128]
    sgemm64<0><<<dim3(H2_ / 64, NN / 64, B_), blk>>>(
        fc2, h2, g2, NN, H2_, NN,
        (long long)NN * NN, (long long)NN * H2_, (long long)NN * H2_);

    // ===== Head: out = leaky(fc2 @ (g2 @ Wg) + bg) =====
    gv_kernel<<<rowsTot / 8, 256>>>(g2, Wg, gv);
    z_kernel<<<rowsTot / 8, 256>>>(fc2, gv, bg, out);
}

// round 2
// speedup vs baseline: 1.0483x; 1.0483x over previous
#include <cuda_runtime.h>
#include <math.h>

#define B_   32
#define NN   1024
#define FIN  512
#define H1_  256
#define H2_  128

typedef unsigned long long ull;

// ---------------- scratch (device globals; no allocation allowed) ----------
__device__ float d_h1[B_ * NN * H1_];
__device__ float d_g1[B_ * NN * H1_];
__device__ float d_h2[B_ * NN * H2_];
__device__ float d_att1[(long long)B_ * NN * NN];
__device__ float d_el[B_ * NN];
__device__ float d_er[B_ * NN];
__device__ float d_stat[B_ * 2];
__device__ float d_gv[B_ * NN];

__device__ __forceinline__ ull dup2(float x) {
    ull d;
    unsigned u = __float_as_uint(x);
    asm("mov.b64 %0, {%1, %1};" : "=l"(d) : "r"(u));
    return d;
}
__device__ __forceinline__ void fma2(ull& acc, ull a, ull b) {
    asm("fma.rn.f32x2 %0, %1, %2, %0;" : "+l"(acc) : "l"(a), "l"(b));
}
__device__ __forceinline__ void unpack2(ull v, float& lo, float& hi) {
    unsigned a, b;
    asm("mov.b64 {%0, %1}, %2;" : "=r"(a), "=r"(b) : "l"(v));
    lo = __uint_as_float(a);
    hi = __uint_as_float(b);
}
__device__ __forceinline__ ull pack2(float lo, float hi) {
    ull d;
    asm("mov.b64 %0, {%1, %2};" : "=l"(d) : "r"(__float_as_uint(lo)), "r"(__float_as_uint(hi)));
    return d;
}

// ---------------- packed-f32x2 SGEMM: C[M,N] = A[M,K] @ B[K,N] --------------
// Block tile 64(M) x 128(N), BK=16, 256 threads, 4x8 per thread (4 f32x2 pairs).
// Thread tx owns column pairs {n0 + tx*2 + 32*j}, j=0..3 (conflict-free LDS.64).
// EPI: 0 = none, 1 = ELU.
template <int EPI>
__global__ void sgemm128(const float* __restrict__ A, const float* __restrict__ B,
                         float* __restrict__ C, int M, int N, int K,
                         long long sA, long long sB, long long sC)
{
    __shared__ float As[16][64];
    __shared__ float Bs[16][128];

    A += (long long)blockIdx.z * sA;
    B += (long long)blockIdx.z * sB;
    C += (long long)blockIdx.z * sC;

    const int m0 = blockIdx.y * 64;
    const int n0 = blockIdx.x * 128;
    const int tid = threadIdx.x;
    const int tx = tid & 15;          // column-pair group
    const int ty = tid >> 4;          // 4 rows each

    const int arow = tid >> 2;        // 0..63
    const int aq   = (tid & 3) * 4;   // k offset
    const int brow = tid >> 4;        // 0..15
    const int bcol = (tid & 15) * 8;  // 0..120

    ull acc[4][4] = {};               // [row][colpair]

    for (int k0 = 0; k0 < K; k0 += 16) {
        float4 av = *(const float4*)&A[(long long)(m0 + arow) * K + k0 + aq];
        const float* Bg = &B[(long long)(k0 + brow) * N + n0 + bcol];
        float4 bv0 = *(const float4*)Bg;
        float4 bv1 = *(const float4*)(Bg + 4);
        As[aq + 0][arow] = av.x;
        As[aq + 1][arow] = av.y;
        As[aq + 2][arow] = av.z;
        As[aq + 3][arow] = av.w;
        *(float4*)&Bs[brow][bcol]     = bv0;
        *(float4*)&Bs[brow][bcol + 4] = bv1;
        __syncthreads();

#pragma unroll
        for (int k = 0; k < 16; k++) {
            float4 a = *(const float4*)&As[k][ty * 4];
            ull a0 = dup2(a.x), a1 = dup2(a.y), a2 = dup2(a.z), a3 = dup2(a.w);
            const float* brp = &Bs[k][tx * 2];
            ull b0 = *(const ull*)(brp);
            ull b1 = *(const ull*)(brp + 32);
            ull b2 = *(const ull*)(brp + 64);
            ull b3 = *(const ull*)(brp + 96);
            fma2(acc[0][0], a0, b0); fma2(acc[0][1], a0, b1);
            fma2(acc[0][2], a0, b2); fma2(acc[0][3], a0, b3);
            fma2(acc[1][0], a1, b0); fma2(acc[1][1], a1, b1);
            fma2(acc[1][2], a1, b2); fma2(acc[1][3], a1, b3);
            fma2(acc[2][0], a2, b0); fma2(acc[2][1], a2, b1);
            fma2(acc[2][2], a2, b2); fma2(acc[2][3], a2, b3);
            fma2(acc[3][0], a3, b0); fma2(acc[3][1], a3, b1);
            fma2(acc[3][2], a3, b2); fma2(acc[3][3], a3, b3);
        }
        __syncthreads();
    }

#pragma unroll
    for (int i = 0; i < 4; i++) {
        const int m = m0 + ty * 4 + i;
        float* Crow = &C[(long long)m * N + n0 + tx * 2];
#pragma unroll
        for (int j = 0; j < 4; j++) {
            ull v = acc[i][j];
            if (EPI == 1) {
                float lo, hi;
                unpack2(v, lo, hi);
                lo = lo > 0.f ? lo : (__expf(lo) - 1.f);
                hi = hi > 0.f ? hi : (__expf(hi) - 1.f);
                v = pack2(lo, hi);
            }
            *(ull*)(Crow + 32 * j) = v;
        }
    }
}

// ---------------- per-row dual dot: el = h.aL, er = h.aR --------------------
__global__ void rowdot(const float* __restrict__ h, const float* __restrict__ a,
                       float* __restrict__ el, float* __restrict__ er, int Fo)
{
    const int row  = (blockIdx.x * blockDim.x + threadIdx.x) >> 5;
    const int lane = threadIdx.x & 31;
    const float* hp = h + (long long)row * Fo;
    float sl = 0.f, sr = 0.f;
    for (int c = lane; c < Fo; c += 32) {
        float v = hp[c];
        sl = fmaf(v, a[c], sl);
        sr = fmaf(v, a[Fo + c], sr);
    }
#pragma unroll
    for (int o = 16; o; o >>= 1) {
        sl += __shfl_xor_sync(0xFFFFFFFFu, sl, o);
        sr += __shfl_xor_sync(0xFFFFFFFFu, sr, o);
    }
    if (lane == 0) { el[row] = sl; er[row] = sr; }
}

// ---------------- per-batch min/max of separable e --------------------------
__global__ void minmax_stats(const float* __restrict__ el, const float* __restrict__ er,
                             float* __restrict__ stat)
{
    const int b = blockIdx.x;
    const int tid = threadIdx.x;
    float mnl = 1e30f, mxl = -1e30f, mnr = 1e30f, mxr = -1e30f;
    for (int i = tid; i < NN; i += 256) {
        float l = el[b * NN + i], r = er[b * NN + i];
        mnl = fminf(mnl, l); mxl = fmaxf(mxl, l);
        mnr = fminf(mnr, r); mxr = fmaxf(mxr, r);
    }
#pragma unroll
    for (int o = 16; o; o >>= 1) {
        mnl = fminf(mnl, __shfl_xor_sync(0xFFFFFFFFu, mnl, o));
        mxl = fmaxf(mxl, __shfl_xor_sync(0xFFFFFFFFu, mxl, o));
        mnr = fminf(mnr, __shfl_xor_sync(0xFFFFFFFFu, mnr, o));
        mxr = fmaxf(mxr, __shfl_xor_sync(0xFFFFFFFFu, mxr, o));
    }
    __shared__ float s[4][8];
    const int w = tid >> 5, lane = tid & 31;
    if (lane == 0) { s[0][w] = mnl; s[1][w] = mxl; s[2][w] = mnr; s[3][w] = mxr; }
    __syncthreads();
    if (tid == 0) {
        float a0 = s[0][0], a1 = s[1][0], a2 = s[2][0], a3 = s[3][0];
#pragma unroll
        for (int i = 1; i < 8; i++) {
            a0 = fminf(a0, s[0][i]); a1 = fmaxf(a1, s[1][i]);
            a2 = fminf(a2, s[2][i]); a3 = fmaxf(a3, s[3][i]);
        }
        float lo = a0 + a2, hi = a1 + a3;
        float mn = lo >= 0.f ? lo : 0.01f * lo;
        float mx = hi >= 0.f ? hi : 0.01f * hi;
        stat[b * 2 + 0] = mn;
        stat[b * 2 + 1] = 30.f / (mx - mn);
    }
}

// ---------------- attention matrix -------------------------------------------
__global__ void att_kernel(const float* __restrict__ el, const float* __restrict__ er,
                           const float* __restrict__ stat, float* __restrict__ att)
{
    const long long idx = ((long long)blockIdx.x * blockDim.x + threadIdx.x) * 4;
    const int b = (int)(idx >> 20);
    const int i = (int)(idx >> 10) & 1023;
    const int j = (int)idx & 1023;
    const float e  = el[b * NN + i];
    const float mn = stat[b * 2 + 0];
    const float k  = stat[b * 2 + 1];
    float4 r = *(const float4*)&er[b * NN + j];
    float4 o;
    {
        float x = e + r.x; float lr = x >= 0.f ? x : 0.01f * x;
        o.x = 1.f / (1.f + __expf(-(fmaf(lr - mn, k, -20.f))));
    }
    {
        float x = e + r.y; float lr = x >= 0.f ? x : 0.01f * x;
        o.y = 1.f / (1.f + __expf(-(fmaf(lr - mn, k, -20.f))));
    }
    {
        float x = e + r.z; float lr = x >= 0.f ? x : 0.01f * x;
        o.z = 1.f / (1.f + __expf(-(fmaf(lr - mn, k, -20.f))));
    }
    {
        float x = e + r.w; float lr = x >= 0.f ? x : 0.01f * x;
        o.w = 1.f / (1.f + __expf(-(fmaf(lr - mn, k, -20.f))));
    }
    *(float4*)&att[idx] = o;
}

// ---------------- gv = g2 @ Wg ----------------------------------------------
__global__ void gv_kernel(const float* __restrict__ g2, const float* __restrict__ Wg,
                          float* __restrict__ gv)
{
    const int row  = (blockIdx.x * blockDim.x + threadIdx.x) >> 5;
    const int lane = threadIdx.x & 31;
    const float* gp = g2 + (long long)row * H2_;
    float s = fmaf(gp[lane], Wg[lane], gp[lane + 32] * Wg[lane + 32]);
    s = fmaf(gp[lane + 64], Wg[lane + 64], s);
    s = fmaf(gp[lane + 96], Wg[lane + 96], s);
#pragma unroll
    for (int o = 16; o; o >>= 1) s += __shfl_xor_sync(0xFFFFFFFFu, s, o);
    if (lane == 0) gv[row] = s;
}

// ---------------- out = leaky(fc2 @ gv + bg) ----------------------------------
__global__ void z_kernel(const float* __restrict__ fc2, const float* __restrict__ gv,
                         const float* __restrict__ bg, float* __restrict__ out)
{
    const int row  = (blockIdx.x * blockDim.x + threadIdx.x) >> 5;
    const int lane = threadIdx.x & 31;
    const int b = row >> 10;
    const float* fr = fc2 + (long long)row * NN;
    const float* gr = gv + b * NN;
    float s = 0.f;
#pragma unroll
    for (int j = lane * 4; j < NN; j += 128) {
        float4 f = *(const float4*)&fr[j];
        float4 g = *(const float4*)&gr[j];
        s = fmaf(f.x, g.x, s); s = fmaf(f.y, g.y, s);
        s = fmaf(f.z, g.z, s); s = fmaf(f.w, g.w, s);
    }
#pragma unroll
    for (int o = 16; o; o >>= 1) s += __shfl_xor_sync(0xFFFFFFFFu, s, o);
    if (lane == 0) {
        float z = s + bg[0];
        out[row] = z >= 0.f ? z : 0.01f * z;
    }
}

// ---------------------------------------------------------------------------
static float* sym_f(const void* s)
{
    void* p = nullptr;
    cudaGetSymbolAddress(&p, s);
    return (float*)p;
}

extern "C" void kernel_launch(void* const* d_in, const int* in_sizes, int n_in,
                              void* d_out, int out_size)
{
    const float* x  = (const float*)d_in[0];
    const float* W1 = (const float*)d_in[2];
    const float* a1 = (const float*)d_in[3];
    const float* W2 = (const float*)d_in[4];
    const float* a2 = (const float*)d_in[5];
    const float* Wg = (const float*)d_in[6];
    const float* bg = (const float*)d_in[7];

    float* out = (float*)d_out;
    float* fc2 = out + (long long)B_ * NN;
    float* g2  = fc2 + (long long)B_ * NN * NN;

    float* h1   = sym_f(d_h1);
    float* g1   = sym_f(d_g1);
    float* h2   = sym_f(d_h2);
    float* att1 = sym_f(d_att1);
    float* el   = sym_f(d_el);
    float* er   = sym_f(d_er);
    float* stat = sym_f(d_stat);
    float* gv   = sym_f(d_gv);

    const dim3 blk(256);
    const int rowsTot = B_ * NN;           // 32768

    // ===== Layer 1 =====
    sgemm128<0><<<dim3(H1_ / 128, rowsTot / 64, 1), blk>>>(
        x, W1, h1, rowsTot, H1_, FIN, 0, 0, 0);
    rowdot<<<rowsTot / 8, 256>>>(h1, a1, el, er, H1_);
    minmax_stats<<<B_, 256>>>(el, er, stat);
    att_kernel<<<(int)(((long long)B_ * NN * NN / 4) / 256), 256>>>(el, er, stat, att1);
    sgemm128<1><<<dim3(H1_ / 128, NN / 64, B_), blk>>>(
        att1, h1, g1, NN, H1_, NN,
        (long long)NN * NN, (long long)NN * H1_, (long long)NN * H1_);

    // ===== Layer 2 =====
    sgemm128<0><<<dim3(H2_ / 128, rowsTot / 64, 1), blk>>>(
        g1, W2, h2, rowsTot, H2_, H1_, 0, 0, 0);
    rowdot<<<rowsTot / 8, 256>>>(h2, a2, el, er, H2_);
    minmax_stats<<<B_, 256>>>(el, er, stat);
    att_kernel<<<(int)(((long long)B_ * NN * NN / 4) / 256), 256>>>(el, er, stat, fc2);
    sgemm128<0><<<dim3(H2_ / 128, NN / 64, B_), blk>>>(
        fc2, h2, g2, NN, H2_, NN,
        (long long)NN * NN, (long long)NN * H2_, (long long)NN * H2_);

    // ===== Head =====
    gv_kernel<<<rowsTot / 8, 256>>>(g2, Wg, gv);
    z_kernel<<<rowsTot / 8, 256>>>(fc2, gv, bg, out);
}